// round 15
// baseline (speedup 1.0000x reference)
#include <cuda_runtime.h>
#include <cuda_fp16.h>
#include <math.h>
#include <stdint.h>

#define TT 256
#define BB 64
#define II 256
#define HH 256
#define NN 8
#define FF 1024   // 4*H

// ---------------- scratch (device globals; no allocs) ----------------
__device__ int g_flags[TT * NN];
__device__ __align__(16) __half g_xf[(size_t)TT * BB * II];   // X fp16 [m][k]
// h exchange, parity double-buffered: [p][n][b][k] fp16
__device__ __align__(16) __half g_hf[2 * NN * BB * HH];

extern __shared__ char dynsmem[];

// ---------------- helpers ----------------
__device__ __forceinline__ uint32_t smem_u32(const void* p) {
    uint32_t a;
    asm("{ .reg .u64 t; cvta.to.shared.u64 t, %1; cvt.u32.u64 %0, t; }" : "=r"(a) : "l"(p));
    return a;
}

__device__ __forceinline__ void ldsm_x4(uint32_t* r, uint32_t addr) {
    asm volatile("ldmatrix.sync.aligned.m8n8.x4.shared.b16 {%0,%1,%2,%3}, [%4];"
                 : "=r"(r[0]), "=r"(r[1]), "=r"(r[2]), "=r"(r[3]) : "r"(addr));
}

__device__ __forceinline__ void mma_f16(float* c, const uint32_t* a,
                                        uint32_t b0, uint32_t b1) {
    asm volatile(
        "mma.sync.aligned.m16n8k16.row.col.f32.f16.f16.f32 "
        "{%0,%1,%2,%3}, {%4,%5,%6,%7}, {%8,%9}, {%0,%1,%2,%3};"
        : "+f"(c[0]), "+f"(c[1]), "+f"(c[2]), "+f"(c[3])
        : "r"(a[0]), "r"(a[1]), "r"(a[2]), "r"(a[3]), "r"(b0), "r"(b1));
}

__device__ __forceinline__ float fast_sigmoid(float x) {
    return __fdividef(1.f, 1.f + __expf(-x));
}
__device__ __forceinline__ float fast_tanh(float x) {
    return 1.f - __fdividef(2.f, __expf(2.f * x) + 1.f);
}

// ---------------------------------------------------------------------------
// conv_x: X fp32 -> fp16. Also zeroes g_flags.
// ---------------------------------------------------------------------------
__global__ __launch_bounds__(256) void conv_x(const float* __restrict__ x) {
    if (blockIdx.x < 8) g_flags[blockIdx.x * 256 + threadIdx.x] = 0;
    const size_t i0 = ((size_t)blockIdx.x * 256 + threadIdx.x) * 4;
    const float4 v = *(const float4*)(x + i0);
    __half hv[4];
    hv[0] = __float2half(v.x); hv[1] = __float2half(v.y);
    hv[2] = __float2half(v.z); hv[3] = __float2half(v.w);
    *reinterpret_cast<uint2*>(g_xf + i0) = *reinterpret_cast<uint2*>(hv);
}

// ---------------------------------------------------------------------------
// recur_kernel: fused persistent LSTM, single-fp16 HMMA.
// 256 CTAs (jt 0..31, n 0..7), 128 threads = 4 warps (2 b-halves x 2 c-halves),
// occupancy 2 (two CTAs per SM overlap each other's stall phases).
// CTA owns 32 z-cols = 8 h-cols: c = 4*hl + gate -> f = gate*H + jt*8 + hl.
// Step pipeline (R13/R14 structure, flag target 32):
//   ... publish(t-1) -> x-GEMM(t) ks 0-7 -> spin(t-1) -> issue HB cp.async ->
//   x-GEMM(t) ks 8-15 (covers HB fetch) -> wait -> h-GEMM -> stage ->
//   prefetch XB(t+1) -> epilogue -> publish(t).
// ---------------------------------------------------------------------------
#define WSTR   264                  // fp16 elems per smem row (256 + 8 pad)
#define S_WX   0                    // [32][WSTR] fp16 = 16896 B
#define S_WH   16896
#define S_XB   33792                // [64][WSTR] fp16 = 33792 B (row 528 B)
#define S_HB   67584
#define S_ZS   101376               // [64][36] f32 = 9216 B
#define S_TOT  110592

__device__ __forceinline__ void gemm1_acc(
    float acc[2][2][4], uint32_t sbase, uint32_t aB, uint32_t bB,
    int a_row, int a_kof, int b_row, int b_kof,
    int ks_begin, int ks_end)
{
#pragma unroll 4
    for (int ks = ks_begin; ks < ks_end; ks++) {
        const int k0 = ks * 16;
        uint32_t a[2][4], b[4];
#pragma unroll
        for (int ma = 0; ma < 2; ma++)
            ldsm_x4(a[ma], sbase + aB + ((a_row + ma * 16) * WSTR + k0 + a_kof) * 2);
        ldsm_x4(b, sbase + bB + (b_row * WSTR + k0 + b_kof) * 2);
#pragma unroll
        for (int ma = 0; ma < 2; ma++)
#pragma unroll
            for (int nf = 0; nf < 2; nf++)
                mma_f16(acc[ma][nf], a[ma], b[nf * 2], b[nf * 2 + 1]);
    }
}

__global__ __launch_bounds__(128, 2) void recur_kernel(
    const float* __restrict__ w,    // [N, I+H, FF]
    const float* __restrict__ bi,   // [N, FF]
    const float* __restrict__ bh_,  // [N, FF]
    const int*   __restrict__ fd,   // [T*B]
    float* out)                     // [T, N, B, H]
{
    char* sm = dynsmem;
    const uint32_t sbase = smem_u32(sm);
    __half* Wx = (__half*)(sm + S_WX);
    __half* Wh = (__half*)(sm + S_WH);
    float* Zs = (float*)(sm + S_ZS);     // [64][36]

    const int jt = blockIdx.x & 31;      // 0..31 : 8 h-cols each
    const int n  = blockIdx.x >> 5;      // 0..7
    const int tid = threadIdx.x;
    const int wid = tid >> 5, lane = tid & 31;
    const int tx = tid & 7;              // hl_local 0..7
    const int ty = tid >> 3;             // 0..15

    // warp tiling: mw = b-half (32 rows, 2 ma tiles), nw = c-half (16 cols)
    const int mw = wid & 1, nw = wid >> 1;
    const int lrow = lane & 7, lgrp = lane >> 3;
    const int a_row = mw * 32 + (lgrp & 1) * 8 + lrow;   // + ma*16
    const int a_kof = (lgrp >> 1) * 8;
    const int b_row = nw * 16 + (lgrp >> 1) * 8 + lrow;  // 0..31
    const int b_kof = (lgrp & 1) * 8;

    // ---- issue X(0) load first (overlaps weight conversion) ----
    {
#pragma unroll
        for (int i = 0; i < 16; i++) {
            const int id = tid + 128 * i, r = id >> 5, ch = id & 31;
            asm volatile("cp.async.ca.shared.global [%0], [%1], 16;\n"
                         :: "r"(sbase + S_XB + r * 528 + ch * 16),
                            "l"((const void*)(g_xf + (size_t)r * II + ch * 8)));
        }
        asm volatile("cp.async.commit_group;\n");
    }

    // ---- prologue: convert Wx and Wh slices (fp32 -> fp16, K-major) ----
    const float* wxp = w + (size_t)n * (II + HH) * FF;           // k in [0,256)
    const float* whp = wxp + (size_t)II * FF;                    // k in [256,512)
    for (int i = tid; i < 32 * 256; i += 128) {
        const int k = i >> 5, q = i & 31;
        const int g = q >> 3, hl = q & 7;
        const int c = 4 * hl + g;
        const size_t col = (size_t)g * HH + jt * 8 + hl;
        Wx[c * WSTR + k] = __float2half(wxp[(size_t)k * FF + col]);
        Wh[c * WSTR + k] = __float2half(whp[(size_t)k * FF + col]);
    }

    // bias registers: thread's h-column j, 4 gates
    const int j = jt * 8 + tx;
    float bias4[4];
#pragma unroll
    for (int g = 0; g < 4; g++)
        bias4[g] = bi[(size_t)n * FF + g * HH + j] + bh_[(size_t)n * FF + g * HH + j];

    float creg[4] = {0.f, 0.f, 0.f, 0.f};   // rows b = 4*ty + r
    __syncthreads();                         // weights visible

    // XB(0) ready, then first-half x-GEMM(0)
    asm volatile("cp.async.wait_group 0;\n" ::: "memory");
    __syncthreads();

    float acc[2][2][4];
#pragma unroll
    for (int ma = 0; ma < 2; ma++)
#pragma unroll
        for (int nf = 0; nf < 2; nf++)
#pragma unroll
            for (int q = 0; q < 4; q++) acc[ma][nf][q] = 0.f;
    gemm1_acc(acc, sbase, S_XB, S_WX, a_row, a_kof, b_row, b_kof, 0, 8);

    for (int t = 0; t < TT; t++) {
        if (t > 0) {
            // spin on the branch flag (x-half-1 already absorbed most skew)
            int v;
            do {
                asm volatile("ld.acquire.gpu.global.s32 %0, [%1];"
                             : "=r"(v) : "l"(g_flags + (t - 1) * NN + n));
            } while (v < 32);

            // issue cp.async h(t-1) -> HB; latency covered by x-half-2 below
            const __half* sh = g_hf + ((size_t)((t - 1) & 1) * NN + n) * BB * HH;
#pragma unroll
            for (int i = 0; i < 16; i++) {
                const int id = tid + 128 * i, r = id >> 5, ch = id & 31;
                asm volatile("cp.async.ca.shared.global [%0], [%1], 16;\n"
                             :: "r"(sbase + S_HB + r * 528 + ch * 16),
                                "l"((const void*)(sh + (size_t)r * HH + ch * 8)));
            }
            asm volatile("cp.async.commit_group;\n");
        }

        // -- x-GEMM(t) second half: covers the HB L2 fetch --
        gemm1_acc(acc, sbase, S_XB, S_WX, a_row, a_kof, b_row, b_kof, 8, 16);

        if (t > 0) {
            asm volatile("cp.async.wait_group 0;\n" ::: "memory");
            __syncthreads();
            gemm1_acc(acc, sbase, S_HB, S_WH, a_row, a_kof, b_row, b_kof, 0, 16);
        }

        // -- stage z fragments into Zs[b][c] (stride 36) --
#pragma unroll
        for (int ma = 0; ma < 2; ma++)
#pragma unroll
            for (int nf = 0; nf < 2; nf++) {
                const int row = mw * 32 + ma * 16 + (lane >> 2);
                const int col = nw * 16 + nf * 8 + (lane & 3) * 2;
                *(float2*)(Zs + row * 36 + col) =
                    make_float2(acc[ma][nf][0], acc[ma][nf][1]);
                *(float2*)(Zs + (row + 8) * 36 + col) =
                    make_float2(acc[ma][nf][2], acc[ma][nf][3]);
            }
        __syncthreads();

        // -- prefetch X(t+1) into XB (XB free; consumed later this iteration) --
        if (t + 1 < TT) {
            const __half* xs = g_xf + (size_t)(t + 1) * BB * II;
#pragma unroll
            for (int i = 0; i < 16; i++) {
                const int id = tid + 128 * i, r = id >> 5, ch = id & 31;
                asm volatile("cp.async.ca.shared.global [%0], [%1], 16;\n"
                             :: "r"(sbase + S_XB + r * 528 + ch * 16),
                                "l"((const void*)(xs + (size_t)r * II + ch * 8)));
            }
            asm volatile("cp.async.commit_group;\n");
        }

        // -- LSTM epilogue; publish h(t) fp32 (out) + fp16 (exchange) --
        __half* hb = g_hf + ((size_t)(t & 1) * NN + n) * BB * HH;
        const int4 dur4 = *(const int4*)(fd + t * BB + 4 * ty);
        const int durs[4] = {dur4.x, dur4.y, dur4.z, dur4.w};
#pragma unroll
        for (int r = 0; r < 4; r++) {
            const int b = 4 * ty + r;
            const float4 zh = *(const float4*)(Zs + b * 36 + 4 * tx);  // i,f,o,g
            const float zi  = zh.x + bias4[0];
            const float zf_ = zh.y + bias4[1];
            const float zo  = zh.z + bias4[2];
            const float zg_ = zh.w + bias4[3];

            const bool keep = (n > (durs[r] >> 3));

            const float ig = fast_sigmoid(zi);
            const float fg = fast_sigmoid(zf_);
            const float og = fast_sigmoid(zo);
            const float gg = fast_tanh(zg_);

            float cn = fg * creg[r] + ig * gg;
            cn = keep ? creg[r] : cn;
            creg[r] = cn;
            const float hn = og * fast_tanh(cn);

            out[((size_t)(t * NN + n) * BB + b) * HH + j] = hn;
            hb[b * HH + j] = __float2half(hn);
        }

        __syncthreads();   // Zs reads done; h stores issued by all threads

        if (tid == 0) {
            asm volatile("red.release.gpu.global.add.s32 [%0], %1;"
                         :: "l"(g_flags + t * NN + n), "r"(1) : "memory");
        }

        // -- x-GEMM(t+1) first half: absorbs inter-CTA skew before the spin --
        if (t + 1 < TT) {
            asm volatile("cp.async.wait_group 0;\n" ::: "memory");
            __syncthreads();
#pragma unroll
            for (int ma = 0; ma < 2; ma++)
#pragma unroll
                for (int nf = 0; nf < 2; nf++)
#pragma unroll
                    for (int q = 0; q < 4; q++) acc[ma][nf][q] = 0.f;
            gemm1_acc(acc, sbase, S_XB, S_WX, a_row, a_kof, b_row, b_kof, 0, 8);
        }
    }
}

// ---------------------------------------------------------------------------
extern "C" void kernel_launch(void* const* d_in, const int* in_sizes, int n_in,
                              void* d_out, int out_size)
{
    const float* x  = (const float*)d_in[0];   // [T,B,I] f32
    const int*   fd = (const int*)  d_in[1];   // [T,B]   i32
    const float* w  = (const float*)d_in[2];   // [N,I+H,4H] f32
    const float* bi = (const float*)d_in[3];   // [N,4H]
    const float* bh = (const float*)d_in[4];   // [N,4H]
    float* out = (float*)d_out;                // [T,N,B,H]

    conv_x<<<4096, 256>>>(x);

    cudaFuncSetAttribute(recur_kernel, cudaFuncAttributeMaxDynamicSharedMemorySize,
                         S_TOT);
    recur_kernel<<<256, 128, S_TOT>>>(w, bi, bh, fd, out);
}

// round 16
// speedup vs baseline: 1.2042x; 1.2042x over previous
#include <cuda_runtime.h>
#include <cuda_fp16.h>
#include <math.h>
#include <stdint.h>

#define TT 256
#define BB 64
#define II 256
#define HH 256
#define NN 8
#define FF 1024   // 4*H

// ---------------- scratch (device globals; no allocs) ----------------
__device__ int g_flags[TT * NN];
__device__ __align__(16) __half g_xf[(size_t)TT * BB * II];   // X fp16 [m][k]
// h exchange, parity double-buffered: [p][n][b][k] fp16
__device__ __align__(16) __half g_hf[2 * NN * BB * HH];

extern __shared__ char dynsmem[];

// ---------------- helpers ----------------
__device__ __forceinline__ uint32_t smem_u32(const void* p) {
    uint32_t a;
    asm("{ .reg .u64 t; cvta.to.shared.u64 t, %1; cvt.u32.u64 %0, t; }" : "=r"(a) : "l"(p));
    return a;
}

__device__ __forceinline__ void ldsm_x4(uint32_t* r, uint32_t addr) {
    asm volatile("ldmatrix.sync.aligned.m8n8.x4.shared.b16 {%0,%1,%2,%3}, [%4];"
                 : "=r"(r[0]), "=r"(r[1]), "=r"(r[2]), "=r"(r[3]) : "r"(addr));
}

__device__ __forceinline__ void mma_f16(float* c, const uint32_t* a,
                                        uint32_t b0, uint32_t b1) {
    asm volatile(
        "mma.sync.aligned.m16n8k16.row.col.f32.f16.f16.f32 "
        "{%0,%1,%2,%3}, {%4,%5,%6,%7}, {%8,%9}, {%0,%1,%2,%3};"
        : "+f"(c[0]), "+f"(c[1]), "+f"(c[2]), "+f"(c[3])
        : "r"(a[0]), "r"(a[1]), "r"(a[2]), "r"(a[3]), "r"(b0), "r"(b1));
}

// single-MUFU tanh (sm_75+), and sigmoid via tanh: 1 MUFU + mul + fma
__device__ __forceinline__ float approx_tanh(float x) {
    float y;
    asm("tanh.approx.f32 %0, %1;" : "=f"(y) : "f"(x));
    return y;
}
__device__ __forceinline__ float approx_sigmoid(float x) {
    return fmaf(0.5f, approx_tanh(0.5f * x), 0.5f);
}

// ---------------------------------------------------------------------------
// conv_x: X fp32 -> fp16. Also zeroes g_flags.
// ---------------------------------------------------------------------------
__global__ __launch_bounds__(256) void conv_x(const float* __restrict__ x) {
    if (blockIdx.x < 8) g_flags[blockIdx.x * 256 + threadIdx.x] = 0;
    const size_t i0 = ((size_t)blockIdx.x * 256 + threadIdx.x) * 4;
    const float4 v = *(const float4*)(x + i0);
    __half hv[4];
    hv[0] = __float2half(v.x); hv[1] = __float2half(v.y);
    hv[2] = __float2half(v.z); hv[3] = __float2half(v.w);
    *reinterpret_cast<uint2*>(g_xf + i0) = *reinterpret_cast<uint2*>(hv);
}

// ---------------------------------------------------------------------------
// recur_kernel: fused persistent LSTM, single-fp16 HMMA (R14 structure).
// 128 CTAs (jt, n), 256 threads = 8 warps (2 b-halves x 4 c-quarters).
// Step pipeline:
//   ... publish(t-1) -> x-GEMM(t) ks 0-7 (absorbs CTA skew) -> spin(t-1) ->
//   issue HB cp.async -> x-GEMM(t) ks 8-15 (covers HB fetch) -> wait ->
//   h-GEMM -> stage -> prefetch XB(t+1) -> epilogue(hb only) -> publish(t) ->
//   deferred fp32 out stores.
// c ordering: c = 4*hl + gate  ->  f = gate*H + jt*16 + hl.
// ---------------------------------------------------------------------------
#define WSTR   264                  // fp16 elems per smem row (256 + 8 pad)
#define S_WX   0
#define S_WH   33792
#define S_XB   67584
#define S_HB   101376
#define S_ZS   135168               // 64*68*4 = 17408
#define S_TOT  152576

__device__ __forceinline__ void gemm1_acc(
    float acc[2][2][4], uint32_t sbase, uint32_t aB, uint32_t bB,
    int a_row, int a_kof, int b_row, int b_kof,
    int ks_begin, int ks_end)
{
#pragma unroll 4
    for (int ks = ks_begin; ks < ks_end; ks++) {
        const int k0 = ks * 16;
        uint32_t a[2][4], b[4];
#pragma unroll
        for (int ma = 0; ma < 2; ma++)
            ldsm_x4(a[ma], sbase + aB + ((a_row + ma * 16) * WSTR + k0 + a_kof) * 2);
        ldsm_x4(b, sbase + bB + (b_row * WSTR + k0 + b_kof) * 2);
#pragma unroll
        for (int ma = 0; ma < 2; ma++)
#pragma unroll
            for (int nf = 0; nf < 2; nf++)
                mma_f16(acc[ma][nf], a[ma], b[nf * 2], b[nf * 2 + 1]);
    }
}

__global__ __launch_bounds__(256, 1) void recur_kernel(
    const float* __restrict__ w,    // [N, I+H, FF]
    const float* __restrict__ bi,   // [N, FF]
    const float* __restrict__ bh_,  // [N, FF]
    const int*   __restrict__ fd,   // [T*B]
    float* out)                     // [T, N, B, H]
{
    char* sm = dynsmem;
    const uint32_t sbase = smem_u32(sm);
    __half* Wx = (__half*)(sm + S_WX);
    __half* Wh = (__half*)(sm + S_WH);
    float* Zs = (float*)(sm + S_ZS);     // [64][68]

    const int jt = blockIdx.x & 15;
    const int n  = blockIdx.x >> 4;
    const int tid = threadIdx.x;
    const int wid = tid >> 5, lane = tid & 31;
    const int tx = tid & 15;
    const int ty = tid >> 4;

    // warp tiling: mw = b-half (32 rows, 2 ma tiles), nw = c-quarter (16)
    const int mw = wid & 1, nw = wid >> 1;
    const int lrow = lane & 7, lgrp = lane >> 3;
    const int a_row = mw * 32 + (lgrp & 1) * 8 + lrow;   // + ma*16
    const int a_kof = (lgrp >> 1) * 8;
    const int b_row = nw * 16 + (lgrp >> 1) * 8 + lrow;
    const int b_kof = (lgrp & 1) * 8;

    // ---- issue X(0) load first (overlaps weight conversion) ----
    {
#pragma unroll
        for (int i = 0; i < 8; i++) {
            const int id = tid + 256 * i, r = id >> 5, ch = id & 31;
            asm volatile("cp.async.ca.shared.global [%0], [%1], 16;\n"
                         :: "r"(sbase + S_XB + r * 528 + ch * 16),
                            "l"((const void*)(g_xf + (size_t)r * II + ch * 8)));
        }
        asm volatile("cp.async.commit_group;\n");
    }

    // ---- prologue: convert Wx and Wh slices (fp32 -> fp16, K-major) ----
    const float* wx = w + (size_t)n * (II + HH) * FF;            // k in [0,256)
    const float* wh = wx + (size_t)II * FF;                      // k in [256,512)
    for (int i = tid; i < 64 * 256; i += 256) {
        const int k = i >> 6, q = i & 63;
        const int g = q >> 4, hl = q & 15;
        const int c = 4 * hl + g;
        const size_t col = (size_t)g * HH + jt * 16 + hl;
        Wx[c * WSTR + k] = __float2half(wx[(size_t)k * FF + col]);
        Wh[c * WSTR + k] = __float2half(wh[(size_t)k * FF + col]);
    }

    // bias registers: thread's column j, 4 gates
    const int j = jt * 16 + tx;
    float bias4[4];
#pragma unroll
    for (int g = 0; g < 4; g++)
        bias4[g] = bi[(size_t)n * FF + g * HH + j] + bh_[(size_t)n * FF + g * HH + j];

    float creg[4] = {0.f, 0.f, 0.f, 0.f};   // rows b = 4*ty + r
    __syncthreads();                         // weights visible

    // XB(0) ready, then first-half x-GEMM(0)
    asm volatile("cp.async.wait_group 0;\n" ::: "memory");
    __syncthreads();

    float acc[2][2][4];
#pragma unroll
    for (int ma = 0; ma < 2; ma++)
#pragma unroll
        for (int nf = 0; nf < 2; nf++)
#pragma unroll
            for (int q = 0; q < 4; q++) acc[ma][nf][q] = 0.f;
    gemm1_acc(acc, sbase, S_XB, S_WX, a_row, a_kof, b_row, b_kof, 0, 8);

    for (int t = 0; t < TT; t++) {
        if (t > 0) {
            // spin on the branch flag (x-half-1 already absorbed most skew)
            int v;
            do {
                asm volatile("ld.acquire.gpu.global.s32 %0, [%1];"
                             : "=r"(v) : "l"(g_flags + (t - 1) * NN + n));
            } while (v < 16);

            // issue cp.async h(t-1) -> HB; latency covered by x-half-2 below
            const __half* sh = g_hf + ((size_t)((t - 1) & 1) * NN + n) * BB * HH;
#pragma unroll
            for (int i = 0; i < 8; i++) {
                const int id = tid + 256 * i, r = id >> 5, ch = id & 31;
                asm volatile("cp.async.ca.shared.global [%0], [%1], 16;\n"
                             :: "r"(sbase + S_HB + r * 528 + ch * 16),
                                "l"((const void*)(sh + (size_t)r * HH + ch * 8)));
            }
            asm volatile("cp.async.commit_group;\n");
        }

        // -- x-GEMM(t) second half: covers the HB L2 fetch --
        gemm1_acc(acc, sbase, S_XB, S_WX, a_row, a_kof, b_row, b_kof, 8, 16);

        if (t > 0) {
            asm volatile("cp.async.wait_group 0;\n" ::: "memory");
            __syncthreads();
            gemm1_acc(acc, sbase, S_HB, S_WH, a_row, a_kof, b_row, b_kof, 0, 16);
        }

        // -- stage z fragments into Zs[b][c] --
#pragma unroll
        for (int ma = 0; ma < 2; ma++)
#pragma unroll
            for (int nf = 0; nf < 2; nf++) {
                const int row = mw * 32 + ma * 16 + (lane >> 2);
                const int col = nw * 16 + nf * 8 + (lane & 3) * 2;
                *(float2*)(Zs + row * 68 + col) =
                    make_float2(acc[ma][nf][0], acc[ma][nf][1]);
                *(float2*)(Zs + (row + 8) * 68 + col) =
                    make_float2(acc[ma][nf][2], acc[ma][nf][3]);
            }
        __syncthreads();

        // -- prefetch X(t+1) into XB (XB free; consumed later this iteration) --
        if (t + 1 < TT) {
            const __half* xs = g_xf + (size_t)(t + 1) * BB * II;
#pragma unroll
            for (int i = 0; i < 8; i++) {
                const int id = tid + 256 * i, r = id >> 5, ch = id & 31;
                asm volatile("cp.async.ca.shared.global [%0], [%1], 16;\n"
                             :: "r"(sbase + S_XB + r * 528 + ch * 16),
                                "l"((const void*)(xs + (size_t)r * II + ch * 8)));
            }
            asm volatile("cp.async.commit_group;\n");
        }

        // -- LSTM epilogue: gates + cell + fp16 publish (critical path),
        //    fp32 out stores deferred past the flag release --
        __half* hb = g_hf + ((size_t)(t & 1) * NN + n) * BB * HH;
        const int4 dur4 = *(const int4*)(fd + t * BB + 4 * ty);
        const int durs[4] = {dur4.x, dur4.y, dur4.z, dur4.w};
        float hnreg[4];
#pragma unroll
        for (int r = 0; r < 4; r++) {
            const int b = 4 * ty + r;
            const float4 zh = *(const float4*)(Zs + b * 68 + 4 * tx);  // i,f,o,g
            const float zi  = zh.x + bias4[0];
            const float zf_ = zh.y + bias4[1];
            const float zo  = zh.z + bias4[2];
            const float zg_ = zh.w + bias4[3];

            const bool keep = (n > (durs[r] >> 3));

            const float ig = approx_sigmoid(zi);
            const float fg = approx_sigmoid(zf_);
            const float og = approx_sigmoid(zo);
            const float gg = approx_tanh(zg_);

            float cn = fg * creg[r] + ig * gg;
            cn = keep ? creg[r] : cn;
            creg[r] = cn;
            const float hn = og * approx_tanh(cn);
            hnreg[r] = hn;

            hb[b * HH + j] = __float2half(hn);
        }

        __syncthreads();   // Zs reads done; hb stores issued by all threads

        if (tid == 0) {
            asm volatile("red.release.gpu.global.add.s32 [%0], %1;"
                         :: "l"(g_flags + t * NN + n), "r"(1) : "memory");
        }

        // -- deferred fp32 out stores (not on the inter-CTA critical path) --
#pragma unroll
        for (int r = 0; r < 4; r++) {
            const int b = 4 * ty + r;
            out[((size_t)(t * NN + n) * BB + b) * HH + j] = hnreg[r];
        }

        // -- x-GEMM(t+1) first half: absorbs inter-CTA skew before the spin --
        if (t + 1 < TT) {
            asm volatile("cp.async.wait_group 0;\n" ::: "memory");
            __syncthreads();
#pragma unroll
            for (int ma = 0; ma < 2; ma++)
#pragma unroll
                for (int nf = 0; nf < 2; nf++)
#pragma unroll
                    for (int q = 0; q < 4; q++) acc[ma][nf][q] = 0.f;
            gemm1_acc(acc, sbase, S_XB, S_WX, a_row, a_kof, b_row, b_kof, 0, 8);
        }
    }
}

// ---------------------------------------------------------------------------
extern "C" void kernel_launch(void* const* d_in, const int* in_sizes, int n_in,
                              void* d_out, int out_size)
{
    const float* x  = (const float*)d_in[0];   // [T,B,I] f32
    const int*   fd = (const int*)  d_in[1];   // [T,B]   i32
    const float* w  = (const float*)d_in[2];   // [N,I+H,4H] f32
    const float* bi = (const float*)d_in[3];   // [N,4H]
    const float* bh = (const float*)d_in[4];   // [N,4H]
    float* out = (float*)d_out;                // [T,N,B,H]

    conv_x<<<4096, 256>>>(x);

    cudaFuncSetAttribute(recur_kernel, cudaFuncAttributeMaxDynamicSharedMemorySize,
                         S_TOT);
    recur_kernel<<<128, 256, S_TOT>>>(w, bi, bh, fd, out);
}

// round 17
// speedup vs baseline: 1.4239x; 1.1825x over previous
#include <cuda_runtime.h>
#include <cuda_fp16.h>
#include <math.h>
#include <stdint.h>

#define TT 256
#define BB 64
#define II 256
#define HH 256
#define NN 8
#define FF 1024   // 4*H

// ---------------- scratch (device globals; no allocs) ----------------
__device__ int g_flags[TT * NN];
__device__ __align__(16) __half g_xf[(size_t)TT * BB * II];   // X fp16 [m][k]
// h exchange, parity double-buffered: [p][n][b][k] fp16
__device__ __align__(16) __half g_hf[2 * NN * BB * HH];

extern __shared__ char dynsmem[];

// ---------------- helpers ----------------
__device__ __forceinline__ uint32_t smem_u32(const void* p) {
    uint32_t a;
    asm("{ .reg .u64 t; cvta.to.shared.u64 t, %1; cvt.u32.u64 %0, t; }" : "=r"(a) : "l"(p));
    return a;
}

__device__ __forceinline__ void ldsm_x4(uint32_t* r, uint32_t addr) {
    asm volatile("ldmatrix.sync.aligned.m8n8.x4.shared.b16 {%0,%1,%2,%3}, [%4];"
                 : "=r"(r[0]), "=r"(r[1]), "=r"(r[2]), "=r"(r[3]) : "r"(addr));
}

__device__ __forceinline__ void mma_f16(float* c, const uint32_t* a,
                                        uint32_t b0, uint32_t b1) {
    asm volatile(
        "mma.sync.aligned.m16n8k16.row.col.f32.f16.f16.f32 "
        "{%0,%1,%2,%3}, {%4,%5,%6,%7}, {%8,%9}, {%0,%1,%2,%3};"
        : "+f"(c[0]), "+f"(c[1]), "+f"(c[2]), "+f"(c[3])
        : "r"(a[0]), "r"(a[1]), "r"(a[2]), "r"(a[3]), "r"(b0), "r"(b1));
}

// single-MUFU tanh (sm_75+), and sigmoid via tanh: 1 MUFU + mul + fma
__device__ __forceinline__ float approx_tanh(float x) {
    float y;
    asm("tanh.approx.f32 %0, %1;" : "=f"(y) : "f"(x));
    return y;
}
__device__ __forceinline__ float approx_sigmoid(float x) {
    return fmaf(0.5f, approx_tanh(0.5f * x), 0.5f);
}

// ---------------------------------------------------------------------------
// conv_x: X fp32 -> fp16. Also zeroes g_flags.
// ---------------------------------------------------------------------------
__global__ __launch_bounds__(256) void conv_x(const float* __restrict__ x) {
    if (blockIdx.x < 8) g_flags[blockIdx.x * 256 + threadIdx.x] = 0;
    const size_t i0 = ((size_t)blockIdx.x * 256 + threadIdx.x) * 4;
    const float4 v = *(const float4*)(x + i0);
    __half hv[4];
    hv[0] = __float2half(v.x); hv[1] = __float2half(v.y);
    hv[2] = __float2half(v.z); hv[3] = __float2half(v.w);
    *reinterpret_cast<uint2*>(g_xf + i0) = *reinterpret_cast<uint2*>(hv);
}

// ---------------------------------------------------------------------------
// recur_kernel: fused persistent LSTM, single-fp16 HMMA, weight fragments
// register-resident (B-operand ldsm eliminated from the steady-state loop).
// 128 CTAs (jt, n), 256 threads = 8 warps (2 b-halves x 4 c-quarters).
// Step pipeline:
//   ... publish(t-1) -> x-GEMM(t) ks 0-7 (absorbs CTA skew) -> spin(t-1) ->
//   issue HB cp.async -> x-GEMM(t) ks 8-15 (covers HB fetch) -> wait ->
//   h-GEMM -> stage -> prefetch XB(t+1) -> epilogue(hb) -> publish(t) ->
//   deferred fp32 out stores.
// c ordering: c = 4*hl + gate  ->  f = gate*H + jt*16 + hl.
// ---------------------------------------------------------------------------
#define WSTR   264                  // fp16 elems per smem row (256 + 8 pad)
#define S_WX   0
#define S_WH   33792
#define S_XB   67584
#define S_HB   101376
#define S_ZS   135168               // 64*68*4 = 17408
#define S_TOT  152576

// A-from-SMEM, B-from-registers GEMM segment (fully unrolled).
template <int KS0, int KS1>
__device__ __forceinline__ void gemm_regB(
    float acc[2][2][4], uint32_t sbase, uint32_t aB,
    const uint32_t bf[16][4],
    int a_row, int a_kof)
{
#pragma unroll
    for (int ks = KS0; ks < KS1; ks++) {
        const int k0 = ks * 16;
        uint32_t a[2][4];
#pragma unroll
        for (int ma = 0; ma < 2; ma++)
            ldsm_x4(a[ma], sbase + aB + ((a_row + ma * 16) * WSTR + k0 + a_kof) * 2);
#pragma unroll
        for (int ma = 0; ma < 2; ma++)
#pragma unroll
            for (int nf = 0; nf < 2; nf++)
                mma_f16(acc[ma][nf], a[ma], bf[ks][nf * 2], bf[ks][nf * 2 + 1]);
    }
}

__global__ __launch_bounds__(256, 1) void recur_kernel(
    const float* __restrict__ w,    // [N, I+H, FF]
    const float* __restrict__ bi,   // [N, FF]
    const float* __restrict__ bh_,  // [N, FF]
    const int*   __restrict__ fd,   // [T*B]
    float* out)                     // [T, N, B, H]
{
    char* sm = dynsmem;
    const uint32_t sbase = smem_u32(sm);
    __half* Wx = (__half*)(sm + S_WX);
    __half* Wh = (__half*)(sm + S_WH);
    float* Zs = (float*)(sm + S_ZS);     // [64][68]

    const int jt = blockIdx.x & 15;
    const int n  = blockIdx.x >> 4;
    const int tid = threadIdx.x;
    const int wid = tid >> 5, lane = tid & 31;
    const int tx = tid & 15;
    const int ty = tid >> 4;

    // warp tiling: mw = b-half (32 rows, 2 ma tiles), nw = c-quarter (16)
    const int mw = wid & 1, nw = wid >> 1;
    const int lrow = lane & 7, lgrp = lane >> 3;
    const int a_row = mw * 32 + (lgrp & 1) * 8 + lrow;   // + ma*16
    const int a_kof = (lgrp >> 1) * 8;
    const int b_row = nw * 16 + (lgrp >> 1) * 8 + lrow;
    const int b_kof = (lgrp & 1) * 8;

    // ---- issue X(0) load first (overlaps weight conversion) ----
    {
#pragma unroll
        for (int i = 0; i < 8; i++) {
            const int id = tid + 256 * i, r = id >> 5, ch = id & 31;
            asm volatile("cp.async.ca.shared.global [%0], [%1], 16;\n"
                         :: "r"(sbase + S_XB + r * 528 + ch * 16),
                            "l"((const void*)(g_xf + (size_t)r * II + ch * 8)));
        }
        asm volatile("cp.async.commit_group;\n");
    }

    // ---- prologue: convert Wx and Wh slices (fp32 -> fp16, K-major) ----
    const float* wx = w + (size_t)n * (II + HH) * FF;            // k in [0,256)
    const float* wh = wx + (size_t)II * FF;                      // k in [256,512)
    for (int i = tid; i < 64 * 256; i += 256) {
        const int k = i >> 6, q = i & 63;
        const int g = q >> 4, hl = q & 15;
        const int c = 4 * hl + g;
        const size_t col = (size_t)g * HH + jt * 16 + hl;
        Wx[c * WSTR + k] = __float2half(wx[(size_t)k * FF + col]);
        Wh[c * WSTR + k] = __float2half(wh[(size_t)k * FF + col]);
    }

    // bias registers: thread's column j, 4 gates
    const int j = jt * 16 + tx;
    float bias4[4];
#pragma unroll
    for (int g = 0; g < 4; g++)
        bias4[g] = bi[(size_t)n * FF + g * HH + j] + bh_[(size_t)n * FF + g * HH + j];

    float creg[4] = {0.f, 0.f, 0.f, 0.f};   // rows b = 4*ty + r
    __syncthreads();                         // weights visible in SMEM

    // ---- hoist weight fragments into registers (time-invariant) ----
    uint32_t bxf[16][4], bhf[16][4];
#pragma unroll
    for (int ks = 0; ks < 16; ks++) {
        ldsm_x4(bxf[ks], sbase + S_WX + (b_row * WSTR + ks * 16 + b_kof) * 2);
        ldsm_x4(bhf[ks], sbase + S_WH + (b_row * WSTR + ks * 16 + b_kof) * 2);
    }

    // XB(0) ready, then first-half x-GEMM(0)
    asm volatile("cp.async.wait_group 0;\n" ::: "memory");
    __syncthreads();

    float acc[2][2][4];
#pragma unroll
    for (int ma = 0; ma < 2; ma++)
#pragma unroll
        for (int nf = 0; nf < 2; nf++)
#pragma unroll
            for (int q = 0; q < 4; q++) acc[ma][nf][q] = 0.f;
    gemm_regB<0, 8>(acc, sbase, S_XB, bxf, a_row, a_kof);

    for (int t = 0; t < TT; t++) {
        if (t > 0) {
            // spin on the branch flag (x-half-1 already absorbed most skew)
            int v;
            do {
                asm volatile("ld.acquire.gpu.global.s32 %0, [%1];"
                             : "=r"(v) : "l"(g_flags + (t - 1) * NN + n));
            } while (v < 16);

            // issue cp.async h(t-1) -> HB; latency covered by x-half-2 below
            const __half* sh = g_hf + ((size_t)((t - 1) & 1) * NN + n) * BB * HH;
#pragma unroll
            for (int i = 0; i < 8; i++) {
                const int id = tid + 256 * i, r = id >> 5, ch = id & 31;
                asm volatile("cp.async.ca.shared.global [%0], [%1], 16;\n"
                             :: "r"(sbase + S_HB + r * 528 + ch * 16),
                                "l"((const void*)(sh + (size_t)r * HH + ch * 8)));
            }
            asm volatile("cp.async.commit_group;\n");
        }

        // -- x-GEMM(t) second half: covers the HB L2 fetch --
        gemm_regB<8, 16>(acc, sbase, S_XB, bxf, a_row, a_kof);

        if (t > 0) {
            asm volatile("cp.async.wait_group 0;\n" ::: "memory");
            __syncthreads();
            gemm_regB<0, 16>(acc, sbase, S_HB, bhf, a_row, a_kof);
        }

        // -- stage z fragments into Zs[b][c] --
#pragma unroll
        for (int ma = 0; ma < 2; ma++)
#pragma unroll
            for (int nf = 0; nf < 2; nf++) {
                const int row = mw * 32 + ma * 16 + (lane >> 2);
                const int col = nw * 16 + nf * 8 + (lane & 3) * 2;
                *(float2*)(Zs + row * 68 + col) =
                    make_float2(acc[ma][nf][0], acc[ma][nf][1]);
                *(float2*)(Zs + (row + 8) * 68 + col) =
                    make_float2(acc[ma][nf][2], acc[ma][nf][3]);
            }
        __syncthreads();

        // -- prefetch X(t+1) into XB (XB free; consumed later this iteration) --
        if (t + 1 < TT) {
            const __half* xs = g_xf + (size_t)(t + 1) * BB * II;
#pragma unroll
            for (int i = 0; i < 8; i++) {
                const int id = tid + 256 * i, r = id >> 5, ch = id & 31;
                asm volatile("cp.async.ca.shared.global [%0], [%1], 16;\n"
                             :: "r"(sbase + S_XB + r * 528 + ch * 16),
                                "l"((const void*)(xs + (size_t)r * II + ch * 8)));
            }
            asm volatile("cp.async.commit_group;\n");
        }

        // -- LSTM epilogue: gates + cell + fp16 publish (critical path),
        //    fp32 out stores deferred past the flag release --
        __half* hb = g_hf + ((size_t)(t & 1) * NN + n) * BB * HH;
        const int4 dur4 = *(const int4*)(fd + t * BB + 4 * ty);
        const int durs[4] = {dur4.x, dur4.y, dur4.z, dur4.w};
        float hnreg[4];
#pragma unroll
        for (int r = 0; r < 4; r++) {
            const int b = 4 * ty + r;
            const float4 zh = *(const float4*)(Zs + b * 68 + 4 * tx);  // i,f,o,g
            const float zi  = zh.x + bias4[0];
            const float zf_ = zh.y + bias4[1];
            const float zo  = zh.z + bias4[2];
            const float zg_ = zh.w + bias4[3];

            const bool keep = (n > (durs[r] >> 3));

            const float ig = approx_sigmoid(zi);
            const float fg = approx_sigmoid(zf_);
            const float og = approx_sigmoid(zo);
            const float gg = approx_tanh(zg_);

            float cn = fg * creg[r] + ig * gg;
            cn = keep ? creg[r] : cn;
            creg[r] = cn;
            const float hn = og * approx_tanh(cn);
            hnreg[r] = hn;

            hb[b * HH + j] = __float2half(hn);
        }

        __syncthreads();   // Zs reads done; hb stores issued by all threads

        if (tid == 0) {
            asm volatile("red.release.gpu.global.add.s32 [%0], %1;"
                         :: "l"(g_flags + t * NN + n), "r"(1) : "memory");
        }

        // -- deferred fp32 out stores (not on the inter-CTA critical path) --
#pragma unroll
        for (int r = 0; r < 4; r++) {
            const int b = 4 * ty + r;
            out[((size_t)(t * NN + n) * BB + b) * HH + j] = hnreg[r];
        }

        // -- x-GEMM(t+1) first half: absorbs inter-CTA skew before the spin --
        if (t + 1 < TT) {
            asm volatile("cp.async.wait_group 0;\n" ::: "memory");
            __syncthreads();
#pragma unroll
            for (int ma = 0; ma < 2; ma++)
#pragma unroll
                for (int nf = 0; nf < 2; nf++)
#pragma unroll
                    for (int q = 0; q < 4; q++) acc[ma][nf][q] = 0.f;
            gemm_regB<0, 8>(acc, sbase, S_XB, bxf, a_row, a_kof);
        }
    }
}

// ---------------------------------------------------------------------------
extern "C" void kernel_launch(void* const* d_in, const int* in_sizes, int n_in,
                              void* d_out, int out_size)
{
    const float* x  = (const float*)d_in[0];   // [T,B,I] f32
    const int*   fd = (const int*)  d_in[1];   // [T,B]   i32
    const float* w  = (const float*)d_in[2];   // [N,I+H,4H] f32
    const float* bi = (const float*)d_in[3];   // [N,4H]
    const float* bh = (const float*)d_in[4];   // [N,4H]
    float* out = (float*)d_out;                // [T,N,B,H]

    conv_x<<<4096, 256>>>(x);

    cudaFuncSetAttribute(recur_kernel, cudaFuncAttributeMaxDynamicSharedMemorySize,
                         S_TOT);
    recur_kernel<<<128, 256, S_TOT>>>(w, bi, bh, fd, out);
}